// round 16
// baseline (speedup 1.0000x reference)
#include <cuda_runtime.h>
#include <cuda.h>
#include <cuda_fp16.h>
#include <math.h>
#include <stdint.h>

// ---------------- problem dims ----------------
#define D0 1024
#define D1 1024
#define D2 512
#define DEG 5
#define KC 6144            // K = 6*1024
#define NT 96              // KC/BK
#define LN_EPS 1e-5f
#define BMAX 16384

#define BM 128
#define BN 128
#define BK 64
#define STAGES 3
#define STAGE_BYTES 32768          // 16KB A + 16KB B
#define SMEM_TOTAL (1024 + STAGES*STAGE_BYTES)
#define NTHREADS 160               // 4 compute warps (64x64 tiles) + 1 producer

// ---------------- device scratch (no allocs allowed) ----------------
__device__ __half g_Ahi[(size_t)BMAX * KC];   // 201 MB
__device__ __half g_W1[(size_t)D1 * KC];
__device__ __half g_W2[(size_t)D2 * KC];
__device__ float g_biasE1[D1];
__device__ float g_biasE2[D2];
__device__ float g_Y1[(size_t)BMAX * D1];

// ---------------- PTX helpers (sm_90-level only; NO tcgen05) ----------------
__device__ __forceinline__ uint32_t elect_one_pred() {
    uint32_t p;
    asm volatile("{\n\t.reg .pred p;\n\telect.sync _|p, 0xFFFFFFFF;\n\tselp.b32 %0, 1, 0, p;\n\t}" : "=r"(p));
    return p;
}
__device__ __forceinline__ uint32_t smem_u32(const void* p) {
    uint32_t a;
    asm("{ .reg .u64 t; cvta.to.shared.u64 t, %1; cvt.u32.u64 %0, t; }" : "=r"(a) : "l"(p));
    return a;
}
#define MBAR_INIT(a, c) asm volatile("mbarrier.init.shared.b64 [%0], %1;" :: "r"(a), "r"(c) : "memory")
#define MBAR_EXPECT_TX(a, b) asm volatile("mbarrier.arrive.expect_tx.shared.b64 _, [%0], %1;" :: "r"(a), "r"(b) : "memory")
#define MBAR_ARRIVE(a) asm volatile("mbarrier.arrive.shared.b64 _, [%0];" :: "r"(a) : "memory")

#define MBAR_WAIT(addr, ph) do { \
    uint32_t _m = (addr), _p = (ph), _d; \
    asm volatile("{\n\t.reg .pred p;\n\tmbarrier.try_wait.parity.acquire.cta.shared::cta.b64 p, [%1], %2;\n\tselp.b32 %0, 1, 0, p;\n\t}" \
        : "=r"(_d) : "r"(_m), "r"(_p) : "memory"); \
    if (!_d) { asm volatile("{\n\t.reg .pred P1;\n\tWL_%=:\n\tmbarrier.try_wait.parity.acquire.cta.shared::cta.b64 P1, [%0], %1, 0x989680;\n\t@P1 bra.uni WD_%=;\n\tbra.uni WL_%=;\n\tWD_%=:\n\t}" \
        :: "r"(_m), "r"(_p) : "memory"); } \
} while (0)

#define MBAR_WAIT_RELAXED(addr, ph) do { \
    uint32_t _m = (addr), _p = (ph), _d; \
    asm volatile("{\n\t.reg .pred p;\n\tmbarrier.try_wait.parity.relaxed.cta.shared::cta.b64 p, [%1], %2, 0x989680;\n\tselp.b32 %0, 1, 0, p;\n\t}" \
        : "=r"(_d) : "r"(_m), "r"(_p) : "memory"); \
    if (!_d) { asm volatile("{\n\t.reg .pred P1;\n\tWL_%=:\n\tmbarrier.try_wait.parity.relaxed.cta.shared::cta.b64 P1, [%0], %1, 0x989680;\n\t@P1 bra.uni WD_%=;\n\tbra.uni WL_%=;\n\tWD_%=:\n\t}" \
        :: "r"(_m), "r"(_p) : "memory"); } \
} while (0)

__device__ __forceinline__ void tma2d(uint32_t dst, const CUtensorMap* map, int x, int y, uint32_t mbar) {
    asm volatile("cp.async.bulk.tensor.2d.shared::cta.global.tile.mbarrier::complete_tx::bytes [%0], [%1, {%2, %3}], [%4];"
        :: "r"(dst), "l"(map), "r"(x), "r"(y), "r"(mbar) : "memory");
}

__device__ __forceinline__ void ldsm4(uint32_t* r, uint32_t addr) {
    asm volatile("ldmatrix.sync.aligned.m8n8.x4.shared.b16 {%0,%1,%2,%3}, [%4];"
        : "=r"(r[0]), "=r"(r[1]), "=r"(r[2]), "=r"(r[3]) : "r"(addr));
}

__device__ __forceinline__ void mma16816(float* c, const uint32_t* a, const uint32_t* b) {
    asm volatile("mma.sync.aligned.m16n8k16.row.col.f32.f16.f16.f32 "
                 "{%0,%1,%2,%3},{%4,%5,%6,%7},{%8,%9},{%0,%1,%2,%3};"
        : "+f"(c[0]), "+f"(c[1]), "+f"(c[2]), "+f"(c[3])
        : "r"(a[0]), "r"(a[1]), "r"(a[2]), "r"(a[3]), "r"(b[0]), "r"(b[1]));
}

// ---------------- math helpers ----------------
__device__ __forceinline__ float tanh_acc(float x) {
    float ax = fminf(fabsf(x), 10.0f);
    float e = __expf(2.0f * ax);
    float r = (e - 1.0f) / (e + 1.0f);
    return copysignf(r, x);
}
__device__ __forceinline__ float blockReduceSum(float v, float* red) {
    int lane = threadIdx.x & 31, w = threadIdx.x >> 5;
    #pragma unroll
    for (int o = 16; o; o >>= 1) v += __shfl_xor_sync(0xffffffffu, v, o);
    __syncthreads();
    if (lane == 0) red[w] = v;
    __syncthreads();
    float t = (lane < (blockDim.x >> 5)) ? red[lane] : 0.0f;
    #pragma unroll
    for (int o = 4; o; o >>= 1) t += __shfl_xor_sync(0xffffffffu, t, o);
    return __shfl_sync(0xffffffffu, t, 0);
}
// compute T1..T5 + passthrough and store as 6 half2 regions
__device__ __forceinline__ void cheb_store2(float h0, float h1, float p0, float p1,
                                            __half* base, int stride, int i) {
    float ta = tanh_acc(h0), tb = tanh_acc(h1);
    float A1 = ta, B1 = tb;
    float A2 = 2.f * ta * ta - 1.f, B2 = 2.f * tb * tb - 1.f;
    float A3 = 2.f * ta * A2 - A1,  B3 = 2.f * tb * B2 - B1;
    float A4 = 2.f * ta * A3 - A2,  B4 = 2.f * tb * B3 - B2;
    float A5 = 2.f * ta * A4 - A3,  B5 = 2.f * tb * B4 - B3;
    *(__half2*)(base + 0 * stride + i) = __floats2half2_rn(A1, B1);
    *(__half2*)(base + 1 * stride + i) = __floats2half2_rn(A2, B2);
    *(__half2*)(base + 2 * stride + i) = __floats2half2_rn(A3, B3);
    *(__half2*)(base + 3 * stride + i) = __floats2half2_rn(A4, B4);
    *(__half2*)(base + 4 * stride + i) = __floats2half2_rn(A5, B5);
    *(__half2*)(base + 5 * stride + i) = __floats2half2_rn(p0, p1);
}

// ---------------- merged prep kernel ----------------
__global__ void prep_kernel(const float* __restrict__ x,
                            const float* __restrict__ coeff1, const float* __restrict__ basew1,
                            const float* __restrict__ bias1,
                            const float* __restrict__ coeff2, const float* __restrict__ basew2,
                            const float* __restrict__ bias2,
                            __half* __restrict__ Ah, __half* __restrict__ W1, __half* __restrict__ W2,
                            float* __restrict__ be1, float* __restrict__ be2, int nbF) {
    __shared__ float red[32];
    int bx = blockIdx.x;
    if (bx < nbF) {
        int idx2 = bx * 256 + threadIdx.x;             // pair index
        int b = idx2 / (D0 / 2), ip = idx2 % (D0 / 2);
        int i = ip * 2;
        float2 xv = *(const float2*)(x + (size_t)b * D0 + i);
        float t1a = tanh_acc(xv.x), t1b = tanh_acc(xv.y);
        __half* ah = Ah + (size_t)b * KC;
        cheb_store2(t1a, t1b, t1a, t1b, ah, D0, i);
        return;
    }
    bx -= nbF;
    if (bx < 4096) {
        int idx = bx * 256 + threadIdx.x;
        int o = idx >> 10, i = idx & 1023;
        const float* c = coeff1 + ((size_t)o * 1024 + i) * (DEG + 1);
        __half* w = W1 + (size_t)o * KC;
        #pragma unroll
        for (int k = 0; k < 5; k++) w[k * 1024 + i] = __float2half_rn(c[k + 1]);
        w[5 * 1024 + i] = __float2half_rn(basew1[(size_t)o * 1024 + i]);
        return;
    }
    bx -= 4096;
    if (bx < 2048) {
        int idx = bx * 256 + threadIdx.x;
        int o = idx >> 10, i = idx & 1023;
        const float* c = coeff2 + ((size_t)o * 1024 + i) * (DEG + 1);
        __half* w = W2 + (size_t)o * KC;
        #pragma unroll
        for (int k = 0; k < 5; k++) w[k * 1024 + i] = __float2half_rn(c[k + 1]);
        w[5 * 1024 + i] = __float2half_rn(basew2[(size_t)o * 1024 + i]);
        return;
    }
    bx -= 2048;
    if (bx < D1) {
        int o = bx;
        float s = 0.0f;
        for (int i = threadIdx.x; i < D0; i += 256)
            s += coeff1[((size_t)o * D0 + i) * (DEG + 1)];
        float tot = blockReduceSum(s, red);
        if (threadIdx.x == 0) be1[o] = bias1[o] + tot;
        return;
    }
    bx -= D1;
    {
        int o = bx;
        float s = 0.0f;
        for (int i = threadIdx.x; i < D1; i += 256)
            s += coeff2[((size_t)o * D1 + i) * (DEG + 1)];
        float tot = blockReduceSum(s, red);
        if (threadIdx.x == 0) be2[o] = bias2[o] + tot;
    }
}

// ---------------- LN + SiLU + layer-2 features (standalone, half2) ----------
__global__ void ln_silu_feat_kernel(const float* __restrict__ Y,
                                    const float* __restrict__ gamma, const float* __restrict__ beta,
                                    __half* __restrict__ Ah) {
    __shared__ float red[32];
    int b = blockIdx.x;
    const float* y = Y + (size_t)b * D1;
    float2 v[2];
    #pragma unroll
    for (int c = 0; c < 2; c++) v[c] = *(const float2*)(y + threadIdx.x * 2 + c * 512);
    float mu = blockReduceSum(v[0].x + v[0].y + v[1].x + v[1].y, red) * (1.0f / (float)D1);
    float q = 0.0f;
    #pragma unroll
    for (int c = 0; c < 2; c++) {
        float dx = v[c].x - mu, dy = v[c].y - mu;
        q += dx * dx + dy * dy;
    }
    float var = blockReduceSum(q, red) * (1.0f / (float)D1);
    float rs = rsqrtf(var + LN_EPS);
    __half* ah = Ah + (size_t)b * KC;
    #pragma unroll
    for (int c = 0; c < 2; c++) {
        int i = threadIdx.x * 2 + c * 512;
        float hn0 = (v[c].x - mu) * rs * gamma[i] + beta[i];
        float hn1 = (v[c].y - mu) * rs * gamma[i + 1] + beta[i + 1];
        float h0 = hn0 * (1.0f / (1.0f + __expf(-hn0)));
        float h1 = hn1 * (1.0f / (1.0f + __expf(-hn1)));
        cheb_store2(h0, h1, h0, h1, ah, D1, i);
    }
}

// ---------------- HMMA GEMM: C[M,N] = A*W^T + biasE ------------------------
// Pure fp16 operands, f32 accum; BM=128 BN=128 BK=64, 3-stage TMA pipe.
// Warp-specialized: warps 0-3 compute (64x64 tiles, 2x2 grid), warp 4 = TMA.
#define SM_FULL(s)  (8u + 8u * (s))
#define SM_EMPTY(s) (40u + 8u * (s))
#define SM_A(s)     (1024u + (s) * STAGE_BYTES)
#define SM_B(s)     (1024u + (s) * STAGE_BYTES + 16384u)

__global__ __launch_bounds__(NTHREADS, 2)
void kan_gemm_kernel(const __grid_constant__ CUtensorMap tma_a,
                     const __grid_constant__ CUtensorMap tma_w,
                     const float* __restrict__ biasE,
                     float* __restrict__ C, int ldc) {
    extern __shared__ __align__(1024) char smem[];
    uint32_t sb = smem_u32(smem);
    int tid = threadIdx.x;
    int wid = tid >> 5, lane = tid & 31;

    if (tid == 0) {
        #pragma unroll
        for (int s = 0; s < STAGES; s++) {
            MBAR_INIT(sb + SM_FULL(s), 1);
            MBAR_INIT(sb + SM_EMPTY(s), 4);
        }
    }
    __syncthreads();

    const int m0 = blockIdx.y * BM;
    const int n0 = blockIdx.x * BN;

    if (wid == 4) {
        // -------- dedicated producer warp --------
        if (elect_one_pred()) {
            int ep = 0;
            for (int ti = 0; ti < NT; ti++) {
                int sp = ti % STAGES;
                if (ti >= STAGES) {
                    MBAR_WAIT_RELAXED(sb + SM_EMPTY(sp), ep);
                    if (sp == STAGES - 1) ep ^= 1;
                }
                MBAR_EXPECT_TX(sb + SM_FULL(sp), STAGE_BYTES);
                int tk = ti * BK;
                tma2d(sb + SM_A(sp), &tma_a, tk, m0, sb + SM_FULL(sp));
                tma2d(sb + SM_B(sp), &tma_w, tk, n0, sb + SM_FULL(sp));
            }
        }
        return;
    }

    // -------- compute warps (0-3): 2x2 grid of 64x64 tiles --------
    int m_w = (wid & 1) * 64;        // warp rows within BM
    int n_w = (wid >> 1) * 64;       // warp cols within BN

    float acc[4][8][4];
    #pragma unroll
    for (int mt = 0; mt < 4; mt++)
        #pragma unroll
        for (int nt = 0; nt < 8; nt++)
            #pragma unroll
            for (int j = 0; j < 4; j++) acc[mt][nt][j] = 0.0f;

    // per-thread ldmatrix addressing (SW128 swizzle: xor term constant/thread)
    int rbase = (lane & 7) + ((lane >> 3) & 1) * 8;
    int hb = ((lane >> 4) & 1) * 16;
    uint32_t xorv = (uint32_t)((lane & 7) << 4);
    uint32_t aoffA = (uint32_t)(m_w + rbase) * 128u;
    uint32_t aoffB = (uint32_t)(n_w + rbase) * 128u;

    int s = 0, pf = 0;
    for (int t = 0; t < NT; t++) {
        MBAR_WAIT(sb + SM_FULL(s), pf);

        uint32_t sA = sb + SM_A(s);
        uint32_t sBt = sb + SM_B(s);
        #pragma unroll
        for (int ks = 0; ks < 4; ks++) {
            uint32_t col = ((uint32_t)(ks * 32 + hb)) ^ xorv;
            uint32_t a[4][4];
            #pragma unroll
            for (int mt = 0; mt < 4; mt++)
                ldsm4(a[mt], sA + aoffA + (uint32_t)mt * 2048u + col);
            uint32_t b[8][2];
            #pragma unroll
            for (int g = 0; g < 4; g++) {
                uint32_t r[4];
                ldsm4(r, sBt + aoffB + (uint32_t)g * 2048u + col);
                b[2 * g][0] = r[0]; b[2 * g][1] = r[2];
                b[2 * g + 1][0] = r[1]; b[2 * g + 1][1] = r[3];
            }
            // stage SMEM is dead after the last ldmatrix of ks==3:
            // release it to the producer before the final MMA chain.
            if (ks == 3 && lane == 0) MBAR_ARRIVE(sb + SM_EMPTY(s));
            #pragma unroll
            for (int mt = 0; mt < 4; mt++)
                #pragma unroll
                for (int nt = 0; nt < 8; nt++)
                    mma16816(acc[mt][nt], a[mt], b[nt]);
        }
        s++;
        if (s == STAGES) { s = 0; pf ^= 1; }
    }

    // epilogue: register fragments -> global, + bias
    const float* bptr = biasE + n0 + n_w;
    #pragma unroll
    for (int mt = 0; mt < 4; mt++) {
        int r0 = m0 + m_w + mt * 16 + (lane >> 2);
        float* c0 = C + (size_t)r0 * ldc + n0 + n_w;
        float* c1 = c0 + 8 * (size_t)ldc;
        #pragma unroll
        for (int nt = 0; nt < 8; nt++) {
            int cidx = nt * 8 + (lane & 3) * 2;
            float bx = bptr[cidx], by = bptr[cidx + 1];
            float2 v0 = make_float2(acc[mt][nt][0] + bx, acc[mt][nt][1] + by);
            float2 v1 = make_float2(acc[mt][nt][2] + bx, acc[mt][nt][3] + by);
            *(float2*)(c0 + cidx) = v0;
            *(float2*)(c1 + cidx) = v1;
        }
    }
}

// ---------------- host ----------------
typedef CUresult (*PFN_encodeTiled)(CUtensorMap*, CUtensorMapDataType, cuuint32_t, void*,
                                    const cuuint64_t*, const cuuint64_t*, const cuuint32_t*, const cuuint32_t*,
                                    CUtensorMapInterleave, CUtensorMapSwizzle, CUtensorMapL2promotion,
                                    CUtensorMapFloatOOBfill);

static void encode_2d(PFN_encodeTiled enc, CUtensorMap* m, void* base,
                      uint64_t d0, uint64_t d1, uint32_t b0, uint32_t b1) {
    cuuint64_t dims[2] = {d0, d1};
    cuuint64_t strides[1] = {d0 * 2};   // fp16 row pitch
    cuuint32_t box[2] = {b0, b1};
    cuuint32_t es[2] = {1, 1};
    enc(m, CU_TENSOR_MAP_DATA_TYPE_FLOAT16, 2, base, dims, strides, box, es,
        CU_TENSOR_MAP_INTERLEAVE_NONE, CU_TENSOR_MAP_SWIZZLE_128B,
        CU_TENSOR_MAP_L2_PROMOTION_L2_128B, CU_TENSOR_MAP_FLOAT_OOB_FILL_NONE);
}

extern "C" void kernel_launch(void* const* d_in, const int* in_sizes, int n_in,
                              void* d_out, int out_size) {
    const float* x      = (const float*)d_in[0];
    const float* coeff1 = (const float*)d_in[1];
    const float* basew1 = (const float*)d_in[2];
    const float* bias1  = (const float*)d_in[3];
    const float* gamma  = (const float*)d_in[4];
    const float* beta   = (const float*)d_in[5];
    const float* coeff2 = (const float*)d_in[6];
    const float* basew2 = (const float*)d_in[7];
    const float* bias2  = (const float*)d_in[8];

    int B = in_sizes[0] / D0;

    void *pAh, *pW1, *pW2, *pB1, *pB2, *pY1;
    cudaGetSymbolAddress(&pAh, g_Ahi);
    cudaGetSymbolAddress(&pW1, g_W1);
    cudaGetSymbolAddress(&pW2, g_W2);
    cudaGetSymbolAddress(&pB1, g_biasE1);
    cudaGetSymbolAddress(&pB2, g_biasE2);
    cudaGetSymbolAddress(&pY1, g_Y1);

    PFN_encodeTiled enc = nullptr;
    cudaDriverEntryPointQueryResult qr;
    cudaGetDriverEntryPointByVersion("cuTensorMapEncodeTiled", (void**)&enc, 12000,
                                     cudaEnableDefault, &qr);

    CUtensorMap tma_a, tma_w1, tma_w2;
    encode_2d(enc, &tma_a, pAh, KC, (uint64_t)B, BK, BM);
    encode_2d(enc, &tma_w1, pW1, KC, D1, BK, BN);
    encode_2d(enc, &tma_w2, pW2, KC, D2, BK, BN);

    cudaFuncSetAttribute(kan_gemm_kernel, cudaFuncAttributeMaxDynamicSharedMemorySize, SMEM_TOTAL);

    // merged prep: feat1 + pack W1/W2 + biasE1/biasE2
    int nbF = B * D0 / 512;   // half2: 2 els per thread, 256 threads/block
    int nblocks = nbF + 4096 + 2048 + D1 + D2;
    prep_kernel<<<nblocks, 256>>>(x, coeff1, basew1, bias1, coeff2, basew2, bias2,
                                  (__half*)pAh, (__half*)pW1, (__half*)pW2,
                                  (float*)pB1, (float*)pB2, nbF);

    // layer 1 GEMM
    kan_gemm_kernel<<<dim3(D1 / BN, B / BM), NTHREADS, SMEM_TOTAL>>>(
        tma_a, tma_w1, (const float*)pB1, (float*)pY1, D1);

    // LN + SiLU + layer-2 features
    ln_silu_feat_kernel<<<B, 256>>>((const float*)pY1, gamma, beta, (__half*)pAh);

    // layer 2 GEMM -> output
    kan_gemm_kernel<<<dim3(D2 / BN, B / BM), NTHREADS, SMEM_TOTAL>>>(
        tma_a, tma_w2, (const float*)pB2, (float*)d_out, D2);
}

// round 17
// speedup vs baseline: 1.2636x; 1.2636x over previous
#include <cuda_runtime.h>
#include <cuda.h>
#include <cuda_fp16.h>
#include <math.h>
#include <stdint.h>

// ---------------- problem dims ----------------
#define D0 1024
#define D1 1024
#define D2 512
#define DEG 5
#define KC 6144            // K = 6*1024
#define NT 96              // KC/BK
#define LN_EPS 1e-5f
#define BMAX 16384

#define BM 128
#define BN 128
#define BK 64
#define STAGES 3
#define STAGE_BYTES 32768          // 16KB A + 16KB B
#define SMEM_TOTAL (1024 + STAGES*STAGE_BYTES)
#define NTHREADS 288               // 8 compute warps + 1 producer warp

// ---------------- device scratch (no allocs allowed) ----------------
__device__ __half g_Ahi[(size_t)BMAX * KC];   // 201 MB
__device__ __half g_W1[(size_t)D1 * KC];
__device__ __half g_W2[(size_t)D2 * KC];
__device__ float g_biasE1[D1];
__device__ float g_biasE2[D2];
__device__ float g_Y1[(size_t)BMAX * D1];

// ---------------- PTX helpers (sm_90-level only; NO tcgen05) ----------------
__device__ __forceinline__ uint32_t elect_one_pred() {
    uint32_t p;
    asm volatile("{\n\t.reg .pred p;\n\telect.sync _|p, 0xFFFFFFFF;\n\tselp.b32 %0, 1, 0, p;\n\t}" : "=r"(p));
    return p;
}
__device__ __forceinline__ uint32_t smem_u32(const void* p) {
    uint32_t a;
    asm("{ .reg .u64 t; cvta.to.shared.u64 t, %1; cvt.u32.u64 %0, t; }" : "=r"(a) : "l"(p));
    return a;
}
#define MBAR_INIT(a, c) asm volatile("mbarrier.init.shared.b64 [%0], %1;" :: "r"(a), "r"(c) : "memory")
#define MBAR_EXPECT_TX(a, b) asm volatile("mbarrier.arrive.expect_tx.shared.b64 _, [%0], %1;" :: "r"(a), "r"(b) : "memory")
#define MBAR_ARRIVE(a) asm volatile("mbarrier.arrive.shared.b64 _, [%0];" :: "r"(a) : "memory")

#define MBAR_WAIT(addr, ph) do { \
    uint32_t _m = (addr), _p = (ph), _d; \
    asm volatile("{\n\t.reg .pred p;\n\tmbarrier.try_wait.parity.acquire.cta.shared::cta.b64 p, [%1], %2;\n\tselp.b32 %0, 1, 0, p;\n\t}" \
        : "=r"(_d) : "r"(_m), "r"(_p) : "memory"); \
    if (!_d) { asm volatile("{\n\t.reg .pred P1;\n\tWL_%=:\n\tmbarrier.try_wait.parity.acquire.cta.shared::cta.b64 P1, [%0], %1, 0x989680;\n\t@P1 bra.uni WD_%=;\n\tbra.uni WL_%=;\n\tWD_%=:\n\t}" \
        :: "r"(_m), "r"(_p) : "memory"); } \
} while (0)

#define MBAR_WAIT_RELAXED(addr, ph) do { \
    uint32_t _m = (addr), _p = (ph), _d; \
    asm volatile("{\n\t.reg .pred p;\n\tmbarrier.try_wait.parity.relaxed.cta.shared::cta.b64 p, [%1], %2, 0x989680;\n\tselp.b32 %0, 1, 0, p;\n\t}" \
        : "=r"(_d) : "r"(_m), "r"(_p) : "memory"); \
    if (!_d) { asm volatile("{\n\t.reg .pred P1;\n\tWL_%=:\n\tmbarrier.try_wait.parity.relaxed.cta.shared::cta.b64 P1, [%0], %1, 0x989680;\n\t@P1 bra.uni WD_%=;\n\tbra.uni WL_%=;\n\tWD_%=:\n\t}" \
        :: "r"(_m), "r"(_p) : "memory"); } \
} while (0)

__device__ __forceinline__ void tma2d(uint32_t dst, const CUtensorMap* map, int x, int y, uint32_t mbar) {
    asm volatile("cp.async.bulk.tensor.2d.shared::cta.global.tile.mbarrier::complete_tx::bytes [%0], [%1, {%2, %3}], [%4];"
        :: "r"(dst), "l"(map), "r"(x), "r"(y), "r"(mbar) : "memory");
}

__device__ __forceinline__ void ldsm4(uint32_t* r, uint32_t addr) {
    asm volatile("ldmatrix.sync.aligned.m8n8.x4.shared.b16 {%0,%1,%2,%3}, [%4];"
        : "=r"(r[0]), "=r"(r[1]), "=r"(r[2]), "=r"(r[3]) : "r"(addr));
}

__device__ __forceinline__ void mma16816(float* c, const uint32_t* a, const uint32_t* b) {
    asm volatile("mma.sync.aligned.m16n8k16.row.col.f32.f16.f16.f32 "
                 "{%0,%1,%2,%3},{%4,%5,%6,%7},{%8,%9},{%0,%1,%2,%3};"
        : "+f"(c[0]), "+f"(c[1]), "+f"(c[2]), "+f"(c[3])
        : "r"(a[0]), "r"(a[1]), "r"(a[2]), "r"(a[3]), "r"(b[0]), "r"(b[1]));
}

// ---------------- math helpers ----------------
__device__ __forceinline__ float tanh_acc(float x) {
    float ax = fminf(fabsf(x), 10.0f);
    float e = __expf(2.0f * ax);
    float r = (e - 1.0f) / (e + 1.0f);
    return copysignf(r, x);
}
__device__ __forceinline__ float blockReduceSum(float v, float* red) {
    int lane = threadIdx.x & 31, w = threadIdx.x >> 5;
    #pragma unroll
    for (int o = 16; o; o >>= 1) v += __shfl_xor_sync(0xffffffffu, v, o);
    __syncthreads();
    if (lane == 0) red[w] = v;
    __syncthreads();
    float t = (lane < (blockDim.x >> 5)) ? red[lane] : 0.0f;
    #pragma unroll
    for (int o = 4; o; o >>= 1) t += __shfl_xor_sync(0xffffffffu, t, o);
    return __shfl_sync(0xffffffffu, t, 0);
}
// compute T1..T5 + passthrough and store as 6 half2 regions
__device__ __forceinline__ void cheb_store2(float h0, float h1, float p0, float p1,
                                            __half* base, int stride, int i) {
    float ta = tanh_acc(h0), tb = tanh_acc(h1);
    float A1 = ta, B1 = tb;
    float A2 = 2.f * ta * ta - 1.f, B2 = 2.f * tb * tb - 1.f;
    float A3 = 2.f * ta * A2 - A1,  B3 = 2.f * tb * B2 - B1;
    float A4 = 2.f * ta * A3 - A2,  B4 = 2.f * tb * B3 - B2;
    float A5 = 2.f * ta * A4 - A3,  B5 = 2.f * tb * B4 - B3;
    *(__half2*)(base + 0 * stride + i) = __floats2half2_rn(A1, B1);
    *(__half2*)(base + 1 * stride + i) = __floats2half2_rn(A2, B2);
    *(__half2*)(base + 2 * stride + i) = __floats2half2_rn(A3, B3);
    *(__half2*)(base + 3 * stride + i) = __floats2half2_rn(A4, B4);
    *(__half2*)(base + 4 * stride + i) = __floats2half2_rn(A5, B5);
    *(__half2*)(base + 5 * stride + i) = __floats2half2_rn(p0, p1);
}

// ---------------- merged prep kernel ----------------
__global__ void prep_kernel(const float* __restrict__ x,
                            const float* __restrict__ coeff1, const float* __restrict__ basew1,
                            const float* __restrict__ bias1,
                            const float* __restrict__ coeff2, const float* __restrict__ basew2,
                            const float* __restrict__ bias2,
                            __half* __restrict__ Ah, __half* __restrict__ W1, __half* __restrict__ W2,
                            float* __restrict__ be1, float* __restrict__ be2, int nbF) {
    __shared__ float red[32];
    int bx = blockIdx.x;
    if (bx < nbF) {
        int idx2 = bx * 256 + threadIdx.x;             // pair index
        int b = idx2 / (D0 / 2), ip = idx2 % (D0 / 2);
        int i = ip * 2;
        float2 xv = *(const float2*)(x + (size_t)b * D0 + i);
        float t1a = tanh_acc(xv.x), t1b = tanh_acc(xv.y);
        __half* ah = Ah + (size_t)b * KC;
        cheb_store2(t1a, t1b, t1a, t1b, ah, D0, i);
        return;
    }
    bx -= nbF;
    if (bx < 4096) {
        int idx = bx * 256 + threadIdx.x;
        int o = idx >> 10, i = idx & 1023;
        const float* c = coeff1 + ((size_t)o * 1024 + i) * (DEG + 1);
        __half* w = W1 + (size_t)o * KC;
        #pragma unroll
        for (int k = 0; k < 5; k++) w[k * 1024 + i] = __float2half_rn(c[k + 1]);
        w[5 * 1024 + i] = __float2half_rn(basew1[(size_t)o * 1024 + i]);
        return;
    }
    bx -= 4096;
    if (bx < 2048) {
        int idx = bx * 256 + threadIdx.x;
        int o = idx >> 10, i = idx & 1023;
        const float* c = coeff2 + ((size_t)o * 1024 + i) * (DEG + 1);
        __half* w = W2 + (size_t)o * KC;
        #pragma unroll
        for (int k = 0; k < 5; k++) w[k * 1024 + i] = __float2half_rn(c[k + 1]);
        w[5 * 1024 + i] = __float2half_rn(basew2[(size_t)o * 1024 + i]);
        return;
    }
    bx -= 2048;
    if (bx < D1) {
        int o = bx;
        float s = 0.0f;
        for (int i = threadIdx.x; i < D0; i += 256)
            s += coeff1[((size_t)o * D0 + i) * (DEG + 1)];
        float tot = blockReduceSum(s, red);
        if (threadIdx.x == 0) be1[o] = bias1[o] + tot;
        return;
    }
    bx -= D1;
    {
        int o = bx;
        float s = 0.0f;
        for (int i = threadIdx.x; i < D1; i += 256)
            s += coeff2[((size_t)o * D1 + i) * (DEG + 1)];
        float tot = blockReduceSum(s, red);
        if (threadIdx.x == 0) be2[o] = bias2[o] + tot;
    }
}

// ---------------- LN + SiLU + layer-2 features (standalone, half2) ----------
__global__ void ln_silu_feat_kernel(const float* __restrict__ Y,
                                    const float* __restrict__ gamma, const float* __restrict__ beta,
                                    __half* __restrict__ Ah) {
    __shared__ float red[32];
    int b = blockIdx.x;
    const float* y = Y + (size_t)b * D1;
    float2 v[2];
    #pragma unroll
    for (int c = 0; c < 2; c++) v[c] = *(const float2*)(y + threadIdx.x * 2 + c * 512);
    float mu = blockReduceSum(v[0].x + v[0].y + v[1].x + v[1].y, red) * (1.0f / (float)D1);
    float q = 0.0f;
    #pragma unroll
    for (int c = 0; c < 2; c++) {
        float dx = v[c].x - mu, dy = v[c].y - mu;
        q += dx * dx + dy * dy;
    }
    float var = blockReduceSum(q, red) * (1.0f / (float)D1);
    float rs = rsqrtf(var + LN_EPS);
    __half* ah = Ah + (size_t)b * KC;
    #pragma unroll
    for (int c = 0; c < 2; c++) {
        int i = threadIdx.x * 2 + c * 512;
        float hn0 = (v[c].x - mu) * rs * gamma[i] + beta[i];
        float hn1 = (v[c].y - mu) * rs * gamma[i + 1] + beta[i + 1];
        float h0 = hn0 * (1.0f / (1.0f + __expf(-hn0)));
        float h1 = hn1 * (1.0f / (1.0f + __expf(-hn1)));
        cheb_store2(h0, h1, h0, h1, ah, D1, i);
    }
}

// ---------------- HMMA GEMM: C[M,N] = A*W^T + biasE ------------------------
// Pure fp16 operands, f32 accum; BM=128 BN=128 BK=64, 3-stage TMA pipe.
// Warp-specialized: warps 0-7 compute (32x64 tiles), warp 8 = TMA producer.
// Inner loop software-pipelines B fragments (one ldsm ahead of the MMA chain).
#define SM_FULL(s)  (8u + 8u * (s))
#define SM_EMPTY(s) (40u + 8u * (s))
#define SM_A(s)     (1024u + (s) * STAGE_BYTES)
#define SM_B(s)     (1024u + (s) * STAGE_BYTES + 16384u)

__global__ __launch_bounds__(NTHREADS, 2)
void kan_gemm_kernel(const __grid_constant__ CUtensorMap tma_a,
                     const __grid_constant__ CUtensorMap tma_w,
                     const float* __restrict__ biasE,
                     float* __restrict__ C, int ldc) {
    extern __shared__ __align__(1024) char smem[];
    uint32_t sb = smem_u32(smem);
    int tid = threadIdx.x;
    int wid = tid >> 5, lane = tid & 31;

    if (tid == 0) {
        #pragma unroll
        for (int s = 0; s < STAGES; s++) {
            MBAR_INIT(sb + SM_FULL(s), 1);
            MBAR_INIT(sb + SM_EMPTY(s), 8);
        }
    }
    __syncthreads();

    const int m0 = blockIdx.y * BM;
    const int n0 = blockIdx.x * BN;

    if (wid == 8) {
        // -------- dedicated producer warp --------
        if (elect_one_pred()) {
            int ep = 0;
            for (int ti = 0; ti < NT; ti++) {
                int sp = ti % STAGES;
                if (ti >= STAGES) {
                    MBAR_WAIT_RELAXED(sb + SM_EMPTY(sp), ep);
                    if (sp == STAGES - 1) ep ^= 1;
                }
                MBAR_EXPECT_TX(sb + SM_FULL(sp), STAGE_BYTES);
                int tk = ti * BK;
                tma2d(sb + SM_A(sp), &tma_a, tk, m0, sb + SM_FULL(sp));
                tma2d(sb + SM_B(sp), &tma_w, tk, n0, sb + SM_FULL(sp));
            }
        }
        return;
    }

    // -------- compute warps (0-7): 32x64 tiles, 4m x 2n grid --------
    int m_w = (wid & 3) * 32;        // warp rows within BM
    int n_w = (wid >> 2) * 64;       // warp cols within BN

    float acc[2][8][4];
    #pragma unroll
    for (int mt = 0; mt < 2; mt++)
        #pragma unroll
        for (int nt = 0; nt < 8; nt++)
            #pragma unroll
            for (int j = 0; j < 4; j++) acc[mt][nt][j] = 0.0f;

    // per-thread ldmatrix addressing (SW128 swizzle: xor term constant/thread)
    int rbase = (lane & 7) + ((lane >> 3) & 1) * 8;
    int hb = ((lane >> 4) & 1) * 16;
    uint32_t xorv = (uint32_t)((lane & 7) << 4);
    uint32_t aoffA = (uint32_t)(m_w + rbase) * 128u;
    uint32_t aoffB = (uint32_t)(n_w + rbase) * 128u;

    // hoisted per-stage base addresses
    uint32_t stA[STAGES], stB[STAGES];
    #pragma unroll
    for (int q = 0; q < STAGES; q++) {
        stA[q] = sb + SM_A(q) + aoffA;
        stB[q] = sb + SM_B(q) + aoffB;
    }

    int s = 0, pf = 0;
    for (int t = 0; t < NT; t++) {
        MBAR_WAIT(sb + SM_FULL(s), pf);

        uint32_t bA = stA[s], bB = stB[s];
        #pragma unroll
        for (int ks = 0; ks < 4; ks++) {
            uint32_t col = ((uint32_t)(ks * 32 + hb)) ^ xorv;
            uint32_t a[2][4];
            ldsm4(a[0], bA + col);
            ldsm4(a[1], bA + 2048u + col);
            // B fragments: one ldsm in flight ahead of each 4-MMA group
            uint32_t r0[4], r1[4];
            ldsm4(r0, bB + col);
            #pragma unroll
            for (int g = 0; g < 4; g++) {
                uint32_t* rc = (g & 1) ? r1 : r0;
                uint32_t* rn = (g & 1) ? r0 : r1;
                if (g < 3) ldsm4(rn, bB + (uint32_t)(g + 1) * 2048u + col);
                // after the last ldsm of the stage, release it to the producer
                if (ks == 3 && g == 3 && lane == 0) MBAR_ARRIVE(sb + SM_EMPTY(s));
                uint32_t b0[2] = {rc[0], rc[2]};
                uint32_t b1[2] = {rc[1], rc[3]};
                mma16816(acc[0][2 * g],     a[0], b0);
                mma16816(acc[1][2 * g],     a[1], b0);
                mma16816(acc[0][2 * g + 1], a[0], b1);
                mma16816(acc[1][2 * g + 1], a[1], b1);
            }
        }
        s++;
        if (s == STAGES) { s = 0; pf ^= 1; }
    }

    // epilogue: register fragments -> global, + bias
    const float* bptr = biasE + n0 + n_w;
    #pragma unroll
    for (int mt = 0; mt < 2; mt++) {
        int r0 = m0 + m_w + mt * 16 + (lane >> 2);
        float* c0 = C + (size_t)r0 * ldc + n0 + n_w;
        float* c1 = c0 + 8 * (size_t)ldc;
        #pragma unroll
        for (int nt = 0; nt < 8; nt++) {
            int cidx = nt * 8 + (lane & 3) * 2;
            float bx = bptr[cidx], by = bptr[cidx + 1];
            float2 v0 = make_float2(acc[mt][nt][0] + bx, acc[mt][nt][1] + by);
            float2 v1 = make_float2(acc[mt][nt][2] + bx, acc[mt][nt][3] + by);
            *(float2*)(c0 + cidx) = v0;
            *(float2*)(c1 + cidx) = v1;
        }
    }
}

// ---------------- host ----------------
typedef CUresult (*PFN_encodeTiled)(CUtensorMap*, CUtensorMapDataType, cuuint32_t, void*,
                                    const cuuint64_t*, const cuuint64_t*, const cuuint32_t*, const cuuint32_t*,
                                    CUtensorMapInterleave, CUtensorMapSwizzle, CUtensorMapL2promotion,
                                    CUtensorMapFloatOOBfill);

static void encode_2d(PFN_encodeTiled enc, CUtensorMap* m, void* base,
                      uint64_t d0, uint64_t d1, uint32_t b0, uint32_t b1) {
    cuuint64_t dims[2] = {d0, d1};
    cuuint64_t strides[1] = {d0 * 2};   // fp16 row pitch
    cuuint32_t box[2] = {b0, b1};
    cuuint32_t es[2] = {1, 1};
    enc(m, CU_TENSOR_MAP_DATA_TYPE_FLOAT16, 2, base, dims, strides, box, es,
        CU_TENSOR_MAP_INTERLEAVE_NONE, CU_TENSOR_MAP_SWIZZLE_128B,
        CU_TENSOR_MAP_L2_PROMOTION_L2_128B, CU_TENSOR_MAP_FLOAT_OOB_FILL_NONE);
}

extern "C" void kernel_launch(void* const* d_in, const int* in_sizes, int n_in,
                              void* d_out, int out_size) {
    const float* x      = (const float*)d_in[0];
    const float* coeff1 = (const float*)d_in[1];
    const float* basew1 = (const float*)d_in[2];
    const float* bias1  = (const float*)d_in[3];
    const float* gamma  = (const float*)d_in[4];
    const float* beta   = (const float*)d_in[5];
    const float* coeff2 = (const float*)d_in[6];
    const float* basew2 = (const float*)d_in[7];
    const float* bias2  = (const float*)d_in[8];

    int B = in_sizes[0] / D0;

    void *pAh, *pW1, *pW2, *pB1, *pB2, *pY1;
    cudaGetSymbolAddress(&pAh, g_Ahi);
    cudaGetSymbolAddress(&pW1, g_W1);
    cudaGetSymbolAddress(&pW2, g_W2);
    cudaGetSymbolAddress(&pB1, g_biasE1);
    cudaGetSymbolAddress(&pB2, g_biasE2);
    cudaGetSymbolAddress(&pY1, g_Y1);

    PFN_encodeTiled enc = nullptr;
    cudaDriverEntryPointQueryResult qr;
    cudaGetDriverEntryPointByVersion("cuTensorMapEncodeTiled", (void**)&enc, 12000,
                                     cudaEnableDefault, &qr);

    CUtensorMap tma_a, tma_w1, tma_w2;
    encode_2d(enc, &tma_a, pAh, KC, (uint64_t)B, BK, BM);
    encode_2d(enc, &tma_w1, pW1, KC, D1, BK, BN);
    encode_2d(enc, &tma_w2, pW2, KC, D2, BK, BN);

    cudaFuncSetAttribute(kan_gemm_kernel, cudaFuncAttributeMaxDynamicSharedMemorySize, SMEM_TOTAL);

    // merged prep: feat1 + pack W1/W2 + biasE1/biasE2
    int nbF = B * D0 / 512;   // half2: 2 els per thread, 256 threads/block
    int nblocks = nbF + 4096 + 2048 + D1 + D2;
    prep_kernel<<<nblocks, 256>>>(x, coeff1, basew1, bias1, coeff2, basew2, bias2,
                                  (__half*)pAh, (__half*)pW1, (__half*)pW2,
                                  (float*)pB1, (float*)pB2, nbF);

    // layer 1 GEMM
    kan_gemm_kernel<<<dim3(D1 / BN, B / BM), NTHREADS, SMEM_TOTAL>>>(
        tma_a, tma_w1, (const float*)pB1, (float*)pY1, D1);

    // LN + SiLU + layer-2 features
    ln_silu_feat_kernel<<<B, 256>>>((const float*)pY1, gamma, beta, (__half*)pAh);

    // layer 2 GEMM -> output
    kan_gemm_kernel<<<dim3(D2 / BN, B / BM), NTHREADS, SMEM_TOTAL>>>(
        tma_a, tma_w2, (const float*)pB2, (float*)d_out, D2);
}